// round 10
// baseline (speedup 1.0000x reference)
#include <cuda_runtime.h>
#include <cuda_bf16.h>
#include <cstdint>

#define NN 100000
#define NE 800000
#define F  128
#define C  64

typedef unsigned long long ull;

// ---- device scratch (no allocations allowed) ----
__device__ float4 g_y4[NN * (C / 4)];   // projected features y = x @ W^T (25.6 MB, L2-resident)
__device__ int    g_head[NN];           // per-dst chain head (0 = empty; e+1 otherwise).
                                        // zero-init at load; k_out restores 0 after use.
__device__ int2   g_link[NE];           // {next_head, src} per edge

// ---------------- build per-destination linked lists (one edge pass) ----------------
__global__ void k_link(const int* __restrict__ src,
                       const int* __restrict__ dst) {
    int e = blockIdx.x * 256 + threadIdx.x;
    if (e < NE) {
        int d = dst[e];
        int old = atomicExch(&g_head[d], e + 1);
        g_link[e] = make_int2(old, src[e]);
    }
}

// ============ tensor-core projection via mma.sync (HMMA, plain PTX ISA) ============
// Per CTA: M=128 nodes (8 warps x 16 rows), N=64 classes, K=128.
// bf16 2-term split: D = Ahi*Bhi + Alo*Bhi + Ahi*Blo  (fp32 accumulate).
#define AS 136
#define ASB (AS * 2)
#define SM_A_HI 0
#define SM_A_LO (128 * ASB)
#define SM_B_HI (2 * 128 * ASB)
#define SM_B_LO (2 * 128 * ASB + 64 * ASB)
#define SM_TOTAL (2 * 128 * ASB + 2 * 64 * ASB)   // 104448

__device__ __forceinline__ uint32_t pack_bf2(__nv_bfloat16 a, __nv_bfloat16 b) {
    return (uint32_t)__bfloat16_as_ushort(a) | ((uint32_t)__bfloat16_as_ushort(b) << 16);
}

__device__ __forceinline__ void mma16816(float* c, const uint32_t* a,
                                         uint32_t b0, uint32_t b1) {
    asm volatile(
        "mma.sync.aligned.m16n8k16.row.col.f32.bf16.bf16.f32 "
        "{%0,%1,%2,%3}, {%4,%5,%6,%7}, {%8,%9}, {%0,%1,%2,%3};"
        : "+f"(c[0]), "+f"(c[1]), "+f"(c[2]), "+f"(c[3])
        : "r"(a[0]), "r"(a[1]), "r"(a[2]), "r"(a[3]), "r"(b0), "r"(b1));
}

__global__ void __launch_bounds__(256, 2) k_gemm_mma(const float* __restrict__ x,
                                                     const float* __restrict__ W) {
    extern __shared__ char smem[];
    int tid = threadIdx.x;
    int base = blockIdx.x * 128;

    for (int i = tid; i < 128 * 32; i += 256) {
        int row = i >> 5, kq = i & 31;
        int gn = base + row;
        float4 v = make_float4(0.f, 0.f, 0.f, 0.f);
        if (gn < NN) v = ((const float4*)x)[(size_t)gn * 32 + kq];
        float e[4] = {v.x, v.y, v.z, v.w};
        __nv_bfloat16 h[4], l[4];
        #pragma unroll
        for (int j = 0; j < 4; j++) {
            h[j] = __float2bfloat16(e[j]);
            l[j] = __float2bfloat16(e[j] - __bfloat162float(h[j]));
        }
        uint32_t off = row * ASB + kq * 8;
        *(ull*)(smem + SM_A_HI + off) =
            (ull)pack_bf2(h[0], h[1]) | ((ull)pack_bf2(h[2], h[3]) << 32);
        *(ull*)(smem + SM_A_LO + off) =
            (ull)pack_bf2(l[0], l[1]) | ((ull)pack_bf2(l[2], l[3]) << 32);
    }
    for (int i = tid; i < 64 * 32; i += 256) {
        int row = i >> 5, kq = i & 31;
        float4 v = ((const float4*)W)[row * 32 + kq];
        float e[4] = {v.x, v.y, v.z, v.w};
        __nv_bfloat16 h[4], l[4];
        #pragma unroll
        for (int j = 0; j < 4; j++) {
            h[j] = __float2bfloat16(e[j]);
            l[j] = __float2bfloat16(e[j] - __bfloat162float(h[j]));
        }
        uint32_t off = row * ASB + kq * 8;
        *(ull*)(smem + SM_B_HI + off) =
            (ull)pack_bf2(h[0], h[1]) | ((ull)pack_bf2(h[2], h[3]) << 32);
        *(ull*)(smem + SM_B_LO + off) =
            (ull)pack_bf2(l[0], l[1]) | ((ull)pack_bf2(l[2], l[3]) << 32);
    }
    __syncthreads();

    int w  = tid >> 5;
    int l  = tid & 31;
    int g  = l >> 2;
    int tg = l & 3;
    int ar0 = w * 16 + g;

    float c[8][4];
    #pragma unroll
    for (int nt = 0; nt < 8; nt++)
        #pragma unroll
        for (int j = 0; j < 4; j++) c[nt][j] = 0.f;

    #pragma unroll
    for (int ks = 0; ks < 8; ks++) {
        int k0 = ks * 16;
        uint32_t aoff = ar0 * ASB + (k0 + tg * 2) * 2;
        uint32_t ah[4], al[4];
        ah[0] = *(const uint32_t*)(smem + SM_A_HI + aoff);
        ah[1] = *(const uint32_t*)(smem + SM_A_HI + aoff + 8 * ASB);
        ah[2] = *(const uint32_t*)(smem + SM_A_HI + aoff + 16);
        ah[3] = *(const uint32_t*)(smem + SM_A_HI + aoff + 8 * ASB + 16);
        al[0] = *(const uint32_t*)(smem + SM_A_LO + aoff);
        al[1] = *(const uint32_t*)(smem + SM_A_LO + aoff + 8 * ASB);
        al[2] = *(const uint32_t*)(smem + SM_A_LO + aoff + 16);
        al[3] = *(const uint32_t*)(smem + SM_A_LO + aoff + 8 * ASB + 16);
        #pragma unroll
        for (int nt = 0; nt < 8; nt++) {
            uint32_t boff = (nt * 8 + g) * ASB + (k0 + tg * 2) * 2;
            uint32_t bh0 = *(const uint32_t*)(smem + SM_B_HI + boff);
            uint32_t bh1 = *(const uint32_t*)(smem + SM_B_HI + boff + 16);
            uint32_t bl0 = *(const uint32_t*)(smem + SM_B_LO + boff);
            uint32_t bl1 = *(const uint32_t*)(smem + SM_B_LO + boff + 16);
            mma16816(c[nt], ah, bh0, bh1);
            mma16816(c[nt], al, bh0, bh1);
            mma16816(c[nt], ah, bl0, bl1);
        }
    }

    float2* yp = (float2*)g_y4;
    int gn0 = base + ar0;
    int gn1 = gn0 + 8;
    #pragma unroll
    for (int nt = 0; nt < 8; nt++) {
        if (gn0 < NN) yp[(size_t)gn0 * 32 + nt * 4 + tg] = make_float2(c[nt][0], c[nt][1]);
        if (gn1 < NN) yp[(size_t)gn1 * 32 + nt * 4 + tg] = make_float2(c[nt][2], c[nt][3]);
    }
}

// ---------------- gather + epilogue via chain walk ----------------
// 16 threads per node; lanes share the (broadcast) chain loads, each owns a float4.
__global__ void __launch_bounds__(256) k_out(const float* __restrict__ bn,
                                             float* __restrict__ out) {
    int tid = threadIdx.x;
    int l  = tid & 15;
    int nl = tid >> 4;
    int v  = blockIdx.x * 16 + nl;     // 6250 * 16 == 100000

    float4 acc = g_y4[(size_t)v * 16 + l];   // self term
    float4 bb = ((const float4*)bn)[l];

    int e = g_head[v];
    if (l == 0) g_head[v] = 0;          // restore invariant for next graph replay

    int deg = 0;
    while (e) {
        int2 ln = g_link[e - 1];        // {next, src} — one 8B broadcast load
        float4 t = g_y4[(size_t)ln.y * 16 + l];
        acc.x += t.x; acc.y += t.y; acc.z += t.z; acc.w += t.w;
        e = ln.x;
        deg++;
    }

    float sc = 1.0f / (float)(deg + 1);
    float4 o;
    o.x = acc.x * sc + bb.x;
    o.y = acc.y * sc + bb.y;
    o.z = acc.z * sc + bb.z;
    o.w = acc.w * sc + bb.w;
    ((float4*)out)[(size_t)v * 16 + l] = o;
}

extern "C" void kernel_launch(void* const* d_in, const int* in_sizes, int n_in,
                              void* d_out, int out_size) {
    const float* x    = (const float*)d_in[0];
    const int*   esrc = (const int*)d_in[1];
    const int*   edst = (const int*)d_in[2];
    const float* W    = (const float*)d_in[3];
    const float* bn   = (const float*)d_in[4];
    float* out = (float*)d_out;

    static cudaStream_t s1 = nullptr;
    static cudaEvent_t ev_root = nullptr, ev_gemm = nullptr;
    if (!s1) {
        cudaStreamCreateWithFlags(&s1, cudaStreamNonBlocking);
        cudaEventCreateWithFlags(&ev_root, cudaEventDisableTiming);
        cudaEventCreateWithFlags(&ev_gemm, cudaEventDisableTiming);
        cudaFuncSetAttribute(k_gemm_mma, cudaFuncAttributeMaxDynamicSharedMemorySize, SM_TOTAL);
    }

    // fork: GEMM on side stream, chain build on main stream
    cudaEventRecord(ev_root, 0);
    cudaStreamWaitEvent(s1, ev_root, 0);
    k_gemm_mma<<<(NN + 127) / 128, 256, SM_TOTAL, s1>>>(x, W);
    cudaEventRecord(ev_gemm, s1);

    k_link<<<(NE + 255) / 256, 256>>>(esrc, edst);

    // join: k_out needs both g_y (gemm) and chains
    cudaStreamWaitEvent(0, ev_gemm, 0);
    k_out<<<NN / 16, 256>>>(bn, out);
}

// round 11
// speedup vs baseline: 1.4537x; 1.4537x over previous
#include <cuda_runtime.h>
#include <cuda_bf16.h>
#include <cstdint>

#define NN 100000
#define NE 800000
#define F  128
#define C  64
#define NBLK 98                 // ceil(100000/1024)
#define VALMASK 0x3FFFFFFF
#define FLAG_A (1 << 30)
#define FLAG_P (2 << 30)

typedef unsigned long long ull;

// ---- device scratch (no allocations allowed) ----
__device__ float4 g_y4[NN * (C / 4)];   // projected features y = x @ W^T (25.6 MB, L2-resident)
__device__ int    g_cnt[NN];            // degree histogram (re-zeroed in k_out)
__device__ int    g_off[NN];            // exclusive offsets; post-scatter = inclusive
__device__ int    g_srcs[NE];           // CSR-by-dst neighbor lists
__device__ int    g_flags[NBLK];        // decoupled-lookback state (re-zeroed in k_out)

// ---------------- degree histogram (scalar, max TLP — round-8 best) ----------------
__global__ void k_count(const int* __restrict__ dst) {
    int e = blockIdx.x * 256 + threadIdx.x;
    if (e < NE) atomicAdd(&g_cnt[dst[e]], 1);
}

// ---------------- single-kernel exclusive scan (decoupled lookback) ----------------
__global__ void __launch_bounds__(1024) k_scan() {
    __shared__ int ws[32];
    __shared__ int s_pref;
    int b = blockIdx.x, t = threadIdx.x;
    int lane = t & 31, wid = t >> 5;
    int i = b * 1024 + t;
    int v = (i < NN) ? g_cnt[i] : 0;

    int incl = v;
    #pragma unroll
    for (int o = 1; o < 32; o <<= 1) {
        int u = __shfl_up_sync(~0u, incl, o);
        if (lane >= o) incl += u;
    }
    if (lane == 31) ws[wid] = incl;
    __syncthreads();
    if (t < 32) {
        int w0 = ws[t];
        int wi = w0;
        #pragma unroll
        for (int o = 1; o < 32; o <<= 1) {
            int u = __shfl_up_sync(~0u, wi, o);
            if (t >= o) wi += u;
        }
        ws[t] = wi - w0;
    }
    __syncthreads();
    int myincl = incl + ws[wid];

    if (t == 1023) {
        int agg = myincl & VALMASK;
        __threadfence();
        atomicExch(&g_flags[b], (b == 0 ? FLAG_P : FLAG_A) | agg);
    }

    if (wid == 0) {
        if (b == 0) {
            if (lane == 0) s_pref = 0;
        } else {
            int pref = 0;
            int w = b;
            while (true) {
                int idx = w - 32 + lane;
                int f = (idx >= 0) ? atomicAdd(&g_flags[idx], 0) : (int)FLAG_P;
                unsigned st = ((unsigned)f) >> 30;
                unsigned pm = __ballot_sync(~0u, st == 2u);
                unsigned vm = __ballot_sync(~0u, st >= 1u);
                if (pm) {
                    int hp = 31 - __clz(pm);
                    unsigned need = ~0u << hp;
                    if ((vm & need) == need) {
                        int contrib = (lane >= hp) ? (f & VALMASK) : 0;
                        #pragma unroll
                        for (int o = 16; o; o >>= 1)
                            contrib += __shfl_down_sync(~0u, contrib, o);
                        pref += __shfl_sync(~0u, contrib, 0);
                        break;
                    }
                } else if (vm == ~0u) {
                    int contrib = f & VALMASK;
                    #pragma unroll
                    for (int o = 16; o; o >>= 1)
                        contrib += __shfl_down_sync(~0u, contrib, o);
                    pref += __shfl_sync(~0u, contrib, 0);
                    w -= 32;
                }
            }
            if (lane == 0) s_pref = pref;
        }
    }
    __syncthreads();
    int pref = s_pref;

    if (t == 1023 && b > 0) {
        __threadfence();
        atomicExch(&g_flags[b], FLAG_P | ((pref + myincl) & VALMASK));
    }

    if (i < NN) g_off[i] = pref + myincl - v;
}

// ---------------- scatter edges (scalar, cursor-free — round-8 best) ----------------
__global__ void k_scatter(const int* __restrict__ src,
                          const int* __restrict__ dst) {
    int e = blockIdx.x * 256 + threadIdx.x;
    if (e < NE) {
        int d = dst[e];
        g_srcs[atomicAdd(&g_off[d], 1)] = src[e];
    }
}

// ============ tensor-core projection: A from GLOBAL registers, B in smem ============
// Per CTA: M=128 nodes (8 warps x 16 rows), N=64 classes, K=128.
// bf16 2-term split: D = Ahi*Bhi + Alo*Bhi + Ahi*Blo  (fp32 accumulate).
// Only B (hi/lo) staged in smem (34.8 KB static) -> ~3 CTAs/SM, high MLP A loads.
#define AS 136
#define ASB (AS * 2)
#define B_LO_OFF (64 * ASB)

__device__ __forceinline__ uint32_t pack_bf2(__nv_bfloat16 a, __nv_bfloat16 b) {
    return (uint32_t)__bfloat16_as_ushort(a) | ((uint32_t)__bfloat16_as_ushort(b) << 16);
}

__device__ __forceinline__ void cvt_hilo(float2 f, uint32_t& hi, uint32_t& lo) {
    __nv_bfloat16 hx = __float2bfloat16(f.x);
    __nv_bfloat16 hy = __float2bfloat16(f.y);
    __nv_bfloat16 lx = __float2bfloat16(f.x - __bfloat162float(hx));
    __nv_bfloat16 ly = __float2bfloat16(f.y - __bfloat162float(hy));
    hi = pack_bf2(hx, hy);
    lo = pack_bf2(lx, ly);
}

__device__ __forceinline__ void mma16816(float* c, const uint32_t* a,
                                         uint32_t b0, uint32_t b1) {
    asm volatile(
        "mma.sync.aligned.m16n8k16.row.col.f32.bf16.bf16.f32 "
        "{%0,%1,%2,%3}, {%4,%5,%6,%7}, {%8,%9}, {%0,%1,%2,%3};"
        : "+f"(c[0]), "+f"(c[1]), "+f"(c[2]), "+f"(c[3])
        : "r"(a[0]), "r"(a[1]), "r"(a[2]), "r"(a[3]), "r"(b0), "r"(b1));
}

__global__ void __launch_bounds__(256) k_gemm_mma(const float* __restrict__ x,
                                                  const float* __restrict__ W) {
    __shared__ char smem[2 * 64 * ASB];   // B hi at 0, B lo at B_LO_OFF
    int tid = threadIdx.x;
    int base = blockIdx.x * 128;

    // ---- fill B (W tile 64x128, split hi/lo). W[class][feat] is K-major. ----
    for (int i = tid; i < 64 * 32; i += 256) {
        int row = i >> 5, kq = i & 31;
        float4 v = ((const float4*)W)[row * 32 + kq];
        uint32_t h0, l0, h1, l1;
        cvt_hilo(make_float2(v.x, v.y), h0, l0);
        cvt_hilo(make_float2(v.z, v.w), h1, l1);
        uint32_t off = row * ASB + kq * 8;
        *(ull*)(smem + off)            = (ull)h0 | ((ull)h1 << 32);
        *(ull*)(smem + B_LO_OFF + off) = (ull)l0 | ((ull)l1 << 32);
    }
    __syncthreads();

    int w  = tid >> 5;
    int l  = tid & 31;
    int g  = l >> 2;       // 0..7
    int tg = l & 3;        // 0..3
    int r0 = base + w * 16 + g;
    int r1 = r0 + 8;
    bool v0 = r0 < NN, v1 = r1 < NN;
    const float* xr0 = x + (size_t)r0 * F;
    const float* xr1 = x + (size_t)r1 * F;

    float c[8][4];
    #pragma unroll
    for (int nt = 0; nt < 8; nt++)
        #pragma unroll
        for (int j = 0; j < 4; j++) c[nt][j] = 0.f;

    const float2 z2 = make_float2(0.f, 0.f);
    #pragma unroll
    for (int ks = 0; ks < 8; ks++) {
        int kA = ks * 16 + tg * 2;
        // 4 independent LDG.64: rows r0/r1 at k and k+8 (fragment layout)
        float2 f0 = v0 ? *(const float2*)(xr0 + kA)     : z2;
        float2 f1 = v1 ? *(const float2*)(xr1 + kA)     : z2;
        float2 f2 = v0 ? *(const float2*)(xr0 + kA + 8) : z2;
        float2 f3 = v1 ? *(const float2*)(xr1 + kA + 8) : z2;
        uint32_t ah[4], al[4];
        cvt_hilo(f0, ah[0], al[0]);
        cvt_hilo(f1, ah[1], al[1]);
        cvt_hilo(f2, ah[2], al[2]);
        cvt_hilo(f3, ah[3], al[3]);
        #pragma unroll
        for (int nt = 0; nt < 8; nt++) {
            uint32_t boff = (nt * 8 + g) * ASB + (ks * 16 + tg * 2) * 2;
            uint32_t bh0 = *(const uint32_t*)(smem + boff);
            uint32_t bh1 = *(const uint32_t*)(smem + boff + 16);
            uint32_t bl0 = *(const uint32_t*)(smem + B_LO_OFF + boff);
            uint32_t bl1 = *(const uint32_t*)(smem + B_LO_OFF + boff + 16);
            mma16816(c[nt], ah, bh0, bh1);
            mma16816(c[nt], al, bh0, bh1);
            mma16816(c[nt], ah, bl0, bl1);
        }
    }

    float2* yp = (float2*)g_y4;
    #pragma unroll
    for (int nt = 0; nt < 8; nt++) {
        if (v0) yp[(size_t)r0 * 32 + nt * 4 + tg] = make_float2(c[nt][0], c[nt][1]);
        if (v1) yp[(size_t)r1 * 32 + nt * 4 + tg] = make_float2(c[nt][2], c[nt][3]);
    }
}

// ---------------- gather + epilogue (CSR, unroll-4 for MLP) ----------------
// Post-scatter, g_off[v] = inclusive offset: jb = v?g_off[v-1]:0, je = g_off[v].
// Re-zeroes g_cnt and g_flags for the next graph replay.
__global__ void __launch_bounds__(256) k_out(const float* __restrict__ bn,
                                             float* __restrict__ out) {
    int tid = threadIdx.x;
    int gt = blockIdx.x * 256 + tid;
    if (gt < NN) g_cnt[gt] = 0;
    if (blockIdx.x == 0 && tid < NBLK) g_flags[tid] = 0;

    int l  = tid & 15;
    int nl = tid >> 4;
    int v  = blockIdx.x * 16 + nl;     // 6250 * 16 == 100000

    float4 acc = g_y4[(size_t)v * 16 + l];   // self term

    int jb = v ? g_off[v - 1] : 0;
    int je = g_off[v];
    int j = jb;
    for (; j + 4 <= je; j += 4) {
        int s0 = g_srcs[j + 0];
        int s1 = g_srcs[j + 1];
        int s2 = g_srcs[j + 2];
        int s3 = g_srcs[j + 3];
        float4 t0 = g_y4[(size_t)s0 * 16 + l];
        float4 t1 = g_y4[(size_t)s1 * 16 + l];
        float4 t2 = g_y4[(size_t)s2 * 16 + l];
        float4 t3 = g_y4[(size_t)s3 * 16 + l];
        acc.x += t0.x + t1.x + t2.x + t3.x;
        acc.y += t0.y + t1.y + t2.y + t3.y;
        acc.z += t0.z + t1.z + t2.z + t3.z;
        acc.w += t0.w + t1.w + t2.w + t3.w;
    }
    for (; j < je; j++) {
        int s = g_srcs[j];
        float4 t = g_y4[(size_t)s * 16 + l];
        acc.x += t.x; acc.y += t.y; acc.z += t.z; acc.w += t.w;
    }

    float sc = 1.0f / (float)(je - jb + 1);
    float4 bb = ((const float4*)bn)[l];
    float4 o;
    o.x = acc.x * sc + bb.x;
    o.y = acc.y * sc + bb.y;
    o.z = acc.z * sc + bb.z;
    o.w = acc.w * sc + bb.w;
    ((float4*)out)[(size_t)v * 16 + l] = o;
}

extern "C" void kernel_launch(void* const* d_in, const int* in_sizes, int n_in,
                              void* d_out, int out_size) {
    const float* x    = (const float*)d_in[0];
    const int*   esrc = (const int*)d_in[1];
    const int*   edst = (const int*)d_in[2];
    const float* W    = (const float*)d_in[3];
    const float* bn   = (const float*)d_in[4];
    float* out = (float*)d_out;

    static cudaStream_t s1 = nullptr;
    static cudaEvent_t ev_root = nullptr, ev_gemm = nullptr;
    if (!s1) {
        cudaStreamCreateWithFlags(&s1, cudaStreamNonBlocking);
        cudaEventCreateWithFlags(&ev_root, cudaEventDisableTiming);
        cudaEventCreateWithFlags(&ev_gemm, cudaEventDisableTiming);
    }

    // fork: GEMM on side stream, CSR build on main stream
    cudaEventRecord(ev_root, 0);
    cudaStreamWaitEvent(s1, ev_root, 0);
    k_gemm_mma<<<(NN + 127) / 128, 256, 0, s1>>>(x, W);
    cudaEventRecord(ev_gemm, s1);

    k_count<<<(NE + 255) / 256, 256>>>(edst);
    k_scan<<<NBLK, 1024>>>();
    k_scatter<<<(NE + 255) / 256, 256>>>(esrc, edst);

    // join: k_out needs both g_y (gemm) and CSR
    cudaStreamWaitEvent(0, ev_gemm, 0);
    k_out<<<NN / 16, 256>>>(bn, out);
}

// round 14
// speedup vs baseline: 1.6623x; 1.1435x over previous
#include <cuda_runtime.h>
#include <cuda_bf16.h>
#include <cuda_fp16.h>
#include <cstdint>

#define NN 100000
#define NE 800000
#define F  128
#define C  64
#define NBLK 98                 // ceil(100000/1024)
#define VALMASK 0x3FFFFFFF
#define FLAG_A (1 << 30)
#define FLAG_P (2 << 30)

typedef unsigned long long ull;

// ---- device scratch (no allocations allowed) ----
__device__ uint4 g_yh[NN * 8];          // y in fp16: 64 halves = 128B/row (12.8 MB, L2-resident)
__device__ int   g_cnt[NN];             // degree histogram (re-zeroed in k_out)
__device__ int   g_off[NN];             // exclusive offsets; post-scatter = inclusive
__device__ int   g_srcs[NE];            // CSR-by-dst neighbor lists
__device__ int   g_flags[NBLK];         // decoupled-lookback state (re-zeroed in k_out)

__device__ __forceinline__ uint32_t h2_bits(__half2 h) {
    uint32_t u;
    __builtin_memcpy(&u, &h, 4);
    return u;
}

// ---------------- degree histogram (scalar, max TLP) ----------------
__global__ void k_count(const int* __restrict__ dst) {
    int e = blockIdx.x * 256 + threadIdx.x;
    if (e < NE) atomicAdd(&g_cnt[dst[e]], 1);
}

// ---------------- single-kernel exclusive scan (decoupled lookback) ----------------
__global__ void __launch_bounds__(1024) k_scan() {
    __shared__ int ws[32];
    __shared__ int s_pref;
    int b = blockIdx.x, t = threadIdx.x;
    int lane = t & 31, wid = t >> 5;
    int i = b * 1024 + t;
    int v = (i < NN) ? g_cnt[i] : 0;

    int incl = v;
    #pragma unroll
    for (int o = 1; o < 32; o <<= 1) {
        int u = __shfl_up_sync(~0u, incl, o);
        if (lane >= o) incl += u;
    }
    if (lane == 31) ws[wid] = incl;
    __syncthreads();
    if (t < 32) {
        int w0 = ws[t];
        int wi = w0;
        #pragma unroll
        for (int o = 1; o < 32; o <<= 1) {
            int u = __shfl_up_sync(~0u, wi, o);
            if (t >= o) wi += u;
        }
        ws[t] = wi - w0;
    }
    __syncthreads();
    int myincl = incl + ws[wid];

    if (t == 1023) {
        int agg = myincl & VALMASK;
        __threadfence();
        atomicExch(&g_flags[b], (b == 0 ? FLAG_P : FLAG_A) | agg);
    }

    if (wid == 0) {
        if (b == 0) {
            if (lane == 0) s_pref = 0;
        } else {
            int pref = 0;
            int w = b;
            while (true) {
                int idx = w - 32 + lane;
                int f = (idx >= 0) ? atomicAdd(&g_flags[idx], 0) : (int)FLAG_P;
                unsigned st = ((unsigned)f) >> 30;
                unsigned pm = __ballot_sync(~0u, st == 2u);
                unsigned vm = __ballot_sync(~0u, st >= 1u);
                if (pm) {
                    int hp = 31 - __clz(pm);
                    unsigned need = ~0u << hp;
                    if ((vm & need) == need) {
                        int contrib = (lane >= hp) ? (f & VALMASK) : 0;
                        #pragma unroll
                        for (int o = 16; o; o >>= 1)
                            contrib += __shfl_down_sync(~0u, contrib, o);
                        pref += __shfl_sync(~0u, contrib, 0);
                        break;
                    }
                } else if (vm == ~0u) {
                    int contrib = f & VALMASK;
                    #pragma unroll
                    for (int o = 16; o; o >>= 1)
                        contrib += __shfl_down_sync(~0u, contrib, o);
                    pref += __shfl_sync(~0u, contrib, 0);
                    w -= 32;
                }
            }
            if (lane == 0) s_pref = pref;
        }
    }
    __syncthreads();
    int pref = s_pref;

    if (t == 1023 && b > 0) {
        __threadfence();
        atomicExch(&g_flags[b], FLAG_P | ((pref + myincl) & VALMASK));
    }

    if (i < NN) g_off[i] = pref + myincl - v;
}

// ---------------- scatter edges (scalar, cursor-free) ----------------
__global__ void k_scatter(const int* __restrict__ src,
                          const int* __restrict__ dst) {
    int e = blockIdx.x * 256 + threadIdx.x;
    if (e < NE) {
        int d = dst[e];
        g_srcs[atomicAdd(&g_off[d], 1)] = src[e];
    }
}

// ============ tensor-core projection: A from GLOBAL registers, B in smem ============
// Per CTA: M=128 nodes (8 warps x 16 rows), N=64 classes, K=128.
// bf16 2-term split: D = Ahi*Bhi + Alo*Bhi + Ahi*Blo  (fp32 accumulate), y stored fp16.
#define AS 136
#define ASB (AS * 2)
#define B_LO_OFF (64 * ASB)

__device__ __forceinline__ uint32_t pack_bf2(__nv_bfloat16 a, __nv_bfloat16 b) {
    return (uint32_t)__bfloat16_as_ushort(a) | ((uint32_t)__bfloat16_as_ushort(b) << 16);
}

__device__ __forceinline__ void cvt_hilo(float2 f, uint32_t& hi, uint32_t& lo) {
    __nv_bfloat16 hx = __float2bfloat16(f.x);
    __nv_bfloat16 hy = __float2bfloat16(f.y);
    __nv_bfloat16 lx = __float2bfloat16(f.x - __bfloat162float(hx));
    __nv_bfloat16 ly = __float2bfloat16(f.y - __bfloat162float(hy));
    hi = pack_bf2(hx, hy);
    lo = pack_bf2(lx, ly);
}

__device__ __forceinline__ void mma16816(float* c, const uint32_t* a,
                                         uint32_t b0, uint32_t b1) {
    asm volatile(
        "mma.sync.aligned.m16n8k16.row.col.f32.bf16.bf16.f32 "
        "{%0,%1,%2,%3}, {%4,%5,%6,%7}, {%8,%9}, {%0,%1,%2,%3};"
        : "+f"(c[0]), "+f"(c[1]), "+f"(c[2]), "+f"(c[3])
        : "r"(a[0]), "r"(a[1]), "r"(a[2]), "r"(a[3]), "r"(b0), "r"(b1));
}

__global__ void __launch_bounds__(256) k_gemm_mma(const float* __restrict__ x,
                                                  const float* __restrict__ W) {
    __shared__ char smem[2 * 64 * ASB];   // B hi at 0, B lo at B_LO_OFF
    int tid = threadIdx.x;
    int base = blockIdx.x * 128;

    for (int i = tid; i < 64 * 32; i += 256) {
        int row = i >> 5, kq = i & 31;
        float4 v = ((const float4*)W)[row * 32 + kq];
        uint32_t h0, l0, h1, l1;
        cvt_hilo(make_float2(v.x, v.y), h0, l0);
        cvt_hilo(make_float2(v.z, v.w), h1, l1);
        uint32_t off = row * ASB + kq * 8;
        *(ull*)(smem + off)            = (ull)h0 | ((ull)h1 << 32);
        *(ull*)(smem + B_LO_OFF + off) = (ull)l0 | ((ull)l1 << 32);
    }
    __syncthreads();

    int w  = tid >> 5;
    int l  = tid & 31;
    int g  = l >> 2;
    int tg = l & 3;
    int r0 = base + w * 16 + g;
    int r1 = r0 + 8;
    bool v0 = r0 < NN, v1 = r1 < NN;
    const float* xr0 = x + (size_t)r0 * F;
    const float* xr1 = x + (size_t)r1 * F;

    float c[8][4];
    #pragma unroll
    for (int nt = 0; nt < 8; nt++)
        #pragma unroll
        for (int j = 0; j < 4; j++) c[nt][j] = 0.f;

    const float2 z2 = make_float2(0.f, 0.f);
    #pragma unroll
    for (int ks = 0; ks < 8; ks++) {
        int kA = ks * 16 + tg * 2;
        float2 f0 = v0 ? *(const float2*)(xr0 + kA)     : z2;
        float2 f1 = v1 ? *(const float2*)(xr1 + kA)     : z2;
        float2 f2 = v0 ? *(const float2*)(xr0 + kA + 8) : z2;
        float2 f3 = v1 ? *(const float2*)(xr1 + kA + 8) : z2;
        uint32_t ah[4], al[4];
        cvt_hilo(f0, ah[0], al[0]);
        cvt_hilo(f1, ah[1], al[1]);
        cvt_hilo(f2, ah[2], al[2]);
        cvt_hilo(f3, ah[3], al[3]);
        #pragma unroll
        for (int nt = 0; nt < 8; nt++) {
            uint32_t boff = (nt * 8 + g) * ASB + (ks * 16 + tg * 2) * 2;
            uint32_t bh0 = *(const uint32_t*)(smem + boff);
            uint32_t bh1 = *(const uint32_t*)(smem + boff + 16);
            uint32_t bl0 = *(const uint32_t*)(smem + B_LO_OFF + boff);
            uint32_t bl1 = *(const uint32_t*)(smem + B_LO_OFF + boff + 16);
            mma16816(c[nt], ah, bh0, bh1);
            mma16816(c[nt], al, bh0, bh1);
            mma16816(c[nt], ah, bl0, bl1);
        }
    }

    // epilogue: pack fp32 accum -> fp16 pairs (u32 index k holds classes 2k,2k+1)
    uint32_t* yh = (uint32_t*)g_yh;
    #pragma unroll
    for (int nt = 0; nt < 8; nt++) {
        if (v0) yh[(size_t)r0 * 32 + nt * 4 + tg] =
            h2_bits(__floats2half2_rn(c[nt][0], c[nt][1]));
        if (v1) yh[(size_t)r1 * 32 + nt * 4 + tg] =
            h2_bits(__floats2half2_rn(c[nt][2], c[nt][3]));
    }
}

// ---------------- gather + epilogue (fp16 rows: 128B/edge, 8 lanes/node) ----------------
__global__ void __launch_bounds__(256) k_out(const float* __restrict__ bn,
                                             float* __restrict__ out) {
    int tid = threadIdx.x;
    int gt = blockIdx.x * 256 + tid;       // 3125 blocks x 256 = 800000 >= NN
    if (gt < NN) g_cnt[gt] = 0;
    if (blockIdx.x == 0 && tid < NBLK) g_flags[tid] = 0;

    int l  = tid & 7;                      // lane owns classes l*8 .. l*8+7
    int nl = tid >> 3;
    int v  = blockIdx.x * 32 + nl;         // 3125 * 32 == 100000

    uint4 sv = g_yh[(size_t)v * 8 + l];    // self term
    float2 a0 = __half22float2(*(const __half2*)&sv.x);
    float2 a1 = __half22float2(*(const __half2*)&sv.y);
    float2 a2 = __half22float2(*(const __half2*)&sv.z);
    float2 a3 = __half22float2(*(const __half2*)&sv.w);

    int jb = v ? g_off[v - 1] : 0;
    int je = g_off[v];
    int j = jb;
    for (; j + 2 <= je; j += 2) {
        int s0 = g_srcs[j];
        int s1 = g_srcs[j + 1];
        uint4 t0 = g_yh[(size_t)s0 * 8 + l];
        uint4 t1 = g_yh[(size_t)s1 * 8 + l];
        float2 p;
        p = __half22float2(*(const __half2*)&t0.x); a0.x += p.x; a0.y += p.y;
        p = __half22float2(*(const __half2*)&t0.y); a1.x += p.x; a1.y += p.y;
        p = __half22float2(*(const __half2*)&t0.z); a2.x += p.x; a2.y += p.y;
        p = __half22float2(*(const __half2*)&t0.w); a3.x += p.x; a3.y += p.y;
        p = __half22float2(*(const __half2*)&t1.x); a0.x += p.x; a0.y += p.y;
        p = __half22float2(*(const __half2*)&t1.y); a1.x += p.x; a1.y += p.y;
        p = __half22float2(*(const __half2*)&t1.z); a2.x += p.x; a2.y += p.y;
        p = __half22float2(*(const __half2*)&t1.w); a3.x += p.x; a3.y += p.y;
    }
    for (; j < je; j++) {
        int s = g_srcs[j];
        uint4 t = g_yh[(size_t)s * 8 + l];
        float2 p;
        p = __half22float2(*(const __half2*)&t.x); a0.x += p.x; a0.y += p.y;
        p = __half22float2(*(const __half2*)&t.y); a1.x += p.x; a1.y += p.y;
        p = __half22float2(*(const __half2*)&t.z); a2.x += p.x; a2.y += p.y;
        p = __half22float2(*(const __half2*)&t.w); a3.x += p.x; a3.y += p.y;
    }

    float sc = 1.0f / (float)(je - jb + 1);
    float4 b0 = ((const float4*)bn)[l * 2];
    float4 b1 = ((const float4*)bn)[l * 2 + 1];
    float4 o0, o1;
    o0.x = a0.x * sc + b0.x;
    o0.y = a0.y * sc + b0.y;
    o0.z = a1.x * sc + b0.z;
    o0.w = a1.y * sc + b0.w;
    o1.x = a2.x * sc + b1.x;
    o1.y = a2.y * sc + b1.y;
    o1.z = a3.x * sc + b1.z;
    o1.w = a3.y * sc + b1.w;
    ((float4*)out)[(size_t)v * 16 + l * 2]     = o0;
    ((float4*)out)[(size_t)v * 16 + l * 2 + 1] = o1;
}

extern "C" void kernel_launch(void* const* d_in, const int* in_sizes, int n_in,
                              void* d_out, int out_size) {
    const float* x    = (const float*)d_in[0];
    const int*   esrc = (const int*)d_in[1];
    const int*   edst = (const int*)d_in[2];
    const float* W    = (const float*)d_in[3];
    const float* bn   = (const float*)d_in[4];
    float* out = (float*)d_out;

    static cudaStream_t s1 = nullptr;
    static cudaEvent_t ev_root = nullptr, ev_gemm = nullptr;
    if (!s1) {
        cudaStreamCreateWithFlags(&s1, cudaStreamNonBlocking);
        cudaEventCreateWithFlags(&ev_root, cudaEventDisableTiming);
        cudaEventCreateWithFlags(&ev_gemm, cudaEventDisableTiming);
    }

    // fork: GEMM on side stream, CSR build on main stream
    cudaEventRecord(ev_root, 0);
    cudaStreamWaitEvent(s1, ev_root, 0);
    k_gemm_mma<<<(NN + 127) / 128, 256, 0, s1>>>(x, W);
    cudaEventRecord(ev_gemm, s1);

    k_count<<<(NE + 255) / 256, 256>>>(edst);
    k_scan<<<NBLK, 1024>>>();
    k_scatter<<<(NE + 255) / 256, 256>>>(esrc, edst);

    // join: k_out needs both g_y (gemm) and CSR
    cudaStreamWaitEvent(0, ev_gemm, 0);
    k_out<<<NN / 32, 256>>>(bn, out);
}